// round 17
// baseline (speedup 1.0000x reference)
#include <cuda_runtime.h>
#include <cuda_fp16.h>
#include <math.h>
#include <stdint.h>

#define L_SEQ   4096
#define D_MODEL 1024
#define N_HEADS 16
#define HEAD_DIM 64
#define P_DIM   128
#define B_SIZE  4
#define M_FULL  (B_SIZE * L_SEQ)   // 16384
#define M_KV    (B_SIZE * P_DIM)   // 512
#define BH      (B_SIZE * N_HEADS) // 64
#define KSLICE  ((size_t)M_KV * D_MODEL)

// ---------------- scratch (static device arrays) ---------------------------
__device__ __half g_x [(size_t)M_FULL * D_MODEL];
__device__ __half g_w [4 * (size_t)D_MODEL * D_MODEL];
__device__ __half g_a [(size_t)M_FULL * D_MODEL];
__device__ __half g_q [(size_t)M_FULL * D_MODEL];   // roped Q, pre-scaled by 0.125

__device__ float g_kvpart[8 * KSLICE];   // [kv*4+ks][m][n]

__device__ __half g_kp[BH * P_DIM * HEAD_DIM];   // K_proj [bh][p][d]
__device__ __half g_vt[BH * HEAD_DIM * P_DIM];   // V_proj^T [bh][d][p]

// ---------------------------------------------------------------------------
// fp32 -> fp16 convert: x + 4 weights in one launch.
// ---------------------------------------------------------------------------
__global__ void __launch_bounds__(256)
convert_all(const float* __restrict__ x,
            const float* __restrict__ w0, const float* __restrict__ w1,
            const float* __restrict__ w2, const float* __restrict__ w3)
{
    const size_t nx = (size_t)M_FULL * D_MODEL / 4;
    const size_t pw = (size_t)D_MODEL * D_MODEL / 4;
    const size_t total = nx + 4 * pw;
    const float* ws[4] = {w0, w1, w2, w3};
    for (size_t i = blockIdx.x * (size_t)blockDim.x + threadIdx.x; i < total;
         i += (size_t)gridDim.x * blockDim.x) {
        float4 v;
        uint2* dst;
        if (i < nx) {
            v = ((const float4*)x)[i];
            dst = (uint2*)g_x + i;
        } else {
            size_t j = i - nx;
            int slot = (int)(j / pw);
            v = ((const float4*)ws[slot])[j - (size_t)slot * pw];
            dst = (uint2*)g_w + j;
        }
        union { __half b[4]; uint2 u; } h;
        h.b[0] = __float2half_rn(v.x); h.b[1] = __float2half_rn(v.y);
        h.b[2] = __float2half_rn(v.z); h.b[3] = __float2half_rn(v.w);
        *dst = h.u;
    }
}

// ---------------------------------------------------------------------------
// mma.sync helpers
// ---------------------------------------------------------------------------
__device__ __forceinline__ uint32_t sptr(const void* p) {
    return (uint32_t)__cvta_generic_to_shared(p);
}
__device__ __forceinline__ void ldm4(uint32_t* r, uint32_t a) {
    asm volatile("ldmatrix.sync.aligned.m8n8.x4.shared.b16 {%0,%1,%2,%3}, [%4];"
                 : "=r"(r[0]), "=r"(r[1]), "=r"(r[2]), "=r"(r[3]) : "r"(a));
}
__device__ __forceinline__ void mma_f16(float* c, const uint32_t* a, uint32_t b0, uint32_t b1) {
    asm volatile(
        "mma.sync.aligned.m16n8k16.row.col.f32.f16.f16.f32 "
        "{%0,%1,%2,%3}, {%4,%5,%6,%7}, {%8,%9}, {%0,%1,%2,%3};"
        : "+f"(c[0]), "+f"(c[1]), "+f"(c[2]), "+f"(c[3])
        : "r"(a[0]), "r"(a[1]), "r"(a[2]), "r"(a[3]), "r"(b0), "r"(b1));
}
__device__ __forceinline__ void cpa16(uint32_t s, const void* g) {
    asm volatile("cp.async.ca.shared.global [%0], [%1], 16;" :: "r"(s), "l"(g));
}
__device__ __forceinline__ void cpa16cg(uint32_t s, const void* g) {
    asm volatile("cp.async.cg.shared.global [%0], [%1], 16;" :: "r"(s), "l"(g));
}
__device__ __forceinline__ uint32_t pack2h(float x, float y) {
    union { __half2 v; uint32_t u; } H;
    H.v = __halves2half2(__float2half_rn(x), __float2half_rn(y));
    return H.u;
}

// ---------------------------------------------------------------------------
// GEMM tile constants: BK=64, stage = {A, B} x 16384 B; 3 stages = 98304 B.
// 128B rows, XOR swizzle c16 ^ (row & 7).
// CTA = 128 threads (4 warps, 2m x 2n, warp tile 64x64) -> 2 CTAs/SM.
// ---------------------------------------------------------------------------
#define MAT_BYTES 16384
#define STG_BYTES (2 * MAT_BYTES)
#define N_STAGE   3
#define SM_GEMM   (N_STAGE * STG_BYTES)   // 98304

__device__ __forceinline__ uint32_t swz128(int row, int c16) {
    return (uint32_t)(row * 128 + ((c16 ^ (row & 7)) << 4));
}

// one k16-step pass over the 64x64 warp tile: 32 independent mma
__device__ __forceinline__ void mma_pass1(
    float acc[4][8][4], uint32_t A[4][4], uint32_t B[4][4])
{
#pragma unroll
    for (int g = 0; g < 4; g++)
#pragma unroll
        for (int mf = 0; mf < 4; mf++) {
            mma_f16(acc[mf][2*g],   A[mf], B[g][0], B[g][2]);
            mma_f16(acc[mf][2*g+1], A[mf], B[g][1], B[g][3]);
        }
}

// Shared GEMM mainloop: BK=64 chunks, 128 threads.
__device__ __forceinline__ void gemm_mainloop(
    char* sbuf, float acc[4][8][4],
    const __half* A, const __half* Bw,
    int m_tile, int n_tile, int kbase, int nch, int gather,
    int tid, int wm, int wn, int lr, int lh)
{
    // per chunk: 2 mats x 128 rows x 8 c16 = 2048 copies; 16/thread
    auto load_chunk = [&](int st, int k0) {
#pragma unroll
        for (int t = 0; t < 16; t++) {
            int idx = tid + t * 128;
            int mtx = idx >> 10;              // 0=A 1=B
            int rem = idx & 1023;
            int row = rem >> 3;
            int c16 = rem & 7;
            int grow;
            if (mtx == 0) {
                int m = m_tile + row;
                grow = gather ? ((m >> 7) * L_SEQ + (m & 127)) : m;
            } else {
                grow = n_tile + row;
            }
            const __half* src = (mtx == 0) ? A : Bw;
            cpa16cg(sptr(sbuf + st * STG_BYTES + mtx * MAT_BYTES + swz128(row, c16)),
                    src + (size_t)grow * 1024 + k0 + c16 * 8);
        }
    };

    load_chunk(0, kbase);
    asm volatile("cp.async.commit_group;" ::: "memory");
    load_chunk(1, kbase + 64);
    asm volatile("cp.async.commit_group;" ::: "memory");

    for (int i = 0; i < nch; i++) {
        if (i < nch - 1) asm volatile("cp.async.wait_group 1;" ::: "memory");
        else             asm volatile("cp.async.wait_group 0;" ::: "memory");
        __syncthreads();
        if (i + 2 < nch) {
            load_chunk((i + 2) % 3, kbase + (i + 2) * 64);
            asm volatile("cp.async.commit_group;" ::: "memory");
        }

        const char* stg = sbuf + (i % 3) * STG_BYTES;

#pragma unroll
        for (int ks = 0; ks < 4; ks++) {
            const int cb = ks * 2 + lh;
            uint32_t af[4][4];
#pragma unroll
            for (int mf = 0; mf < 4; mf++) {
                int row = wm * 64 + mf * 16 + lr;
                ldm4(af[mf], sptr(stg + 0 * MAT_BYTES + swz128(row, cb)));
            }
            uint32_t bf[4][4];
#pragma unroll
            for (int g = 0; g < 4; g++) {
                int row = wn * 64 + g * 16 + lr;
                ldm4(bf[g], sptr(stg + 1 * MAT_BYTES + swz128(row, cb)));
            }
            mma_pass1(acc, af, bf);
        }
    }
}

// ---------------------------------------------------------------------------
// Fused Q-GEMM + split-K KV partials.  Grid (8, 160), 128 threads.
// Q epilogue folds the 1/sqrt(HD)=0.125 attention scale (exact 2^-3 shift).
// ---------------------------------------------------------------------------
__global__ void __launch_bounds__(128, 2)
gemm_q_kv(const float* __restrict__ fcos, const float* __restrict__ fsin)
{
    extern __shared__ char sbuf[];

    const int tid  = threadIdx.x;
    const int warp = tid >> 5;
    const int lane = tid & 31;
    const int wm   = warp & 1;
    const int wn   = warp >> 1;
    const int lr = lane & 15;
    const int lh = lane >> 4;

    float acc[4][8][4];
#pragma unroll
    for (int i = 0; i < 4; i++)
#pragma unroll
        for (int j = 0; j < 8; j++)
#pragma unroll
            for (int q = 0; q < 4; q++) acc[i][j][q] = 0.f;

    const int qpath = (blockIdx.y < 128);
    int m_tile, n_tile, kbase, nch, gather, z = 0;
    const __half* Bw;
    if (qpath) {
        m_tile = blockIdx.y * 128;
        n_tile = blockIdx.x * 128;
        kbase = 0; nch = 16; gather = 0;
        Bw = g_w;                                        // Wq
    } else {
        int idx = (blockIdx.y - 128) * 8 + blockIdx.x;   // 0..255
        z = idx >> 5;                                    // kv*4+ks
        int kv = z >> 2, ks = z & 3;
        m_tile = ((idx >> 3) & 3) * 128;
        n_tile = (idx & 7) * 128;
        kbase = ks * 256; nch = 4; gather = 1;
        Bw = g_w + (size_t)(1 + kv) * D_MODEL * D_MODEL;
    }

    gemm_mainloop(sbuf, acc, g_x, Bw, m_tile, n_tile, kbase, nch, gather,
                  tid, wm, wn, lr, lh);

    const int qrow = lane >> 2;
    const int qcol = (lane & 3) * 2;
    if (qpath) {
#pragma unroll
        for (int mf = 0; mf < 4; mf++)
#pragma unroll
            for (int nf = 0; nf < 8; nf++) {
                int n = n_tile + wn * 64 + nf * 8 + qcol;
#pragma unroll
                for (int hhalf = 0; hhalf < 2; hhalf++) {
                    int m = m_tile + wm * 64 + mf * 16 + qrow + hhalf * 8;
                    float v0 = acc[mf][nf][hhalf * 2];
                    float v1 = acc[mf][nf][hhalf * 2 + 1];
                    int pos = m & (L_SEQ - 1);
                    int j   = (n & 63) >> 1;
                    float c = __ldg(fcos + pos * 32 + j);
                    float s = __ldg(fsin + pos * 32 + j);
                    float o0 = (v0 * c - v1 * s) * 0.125f;
                    float o1 = (v0 * s + v1 * c) * 0.125f;
                    *(uint32_t*)(g_q + (size_t)m * 1024 + n) = pack2h(o0, o1);
                }
            }
    } else {
        float* P = g_kvpart + (size_t)z * KSLICE;
#pragma unroll
        for (int mf = 0; mf < 4; mf++)
#pragma unroll
            for (int nf = 0; nf < 8; nf++) {
                int n = n_tile + wn * 64 + nf * 8 + qcol;
#pragma unroll
                for (int hhalf = 0; hhalf < 2; hhalf++) {
                    int m = m_tile + wm * 64 + mf * 16 + qrow + hhalf * 8;
                    *(float2*)(P + (size_t)m * 1024 + n) =
                        make_float2(acc[mf][nf][hhalf * 2], acc[mf][nf][hhalf * 2 + 1]);
                }
            }
    }
}

// ---------------------------------------------------------------------------
// Standalone Wo GEMM: out = attn @ Wo^T (fp32).  Grid (8, 128), 128 threads.
// ---------------------------------------------------------------------------
__global__ void __launch_bounds__(128, 2)
gemm_wo(float* __restrict__ C)
{
    extern __shared__ char sbuf[];

    const int tid  = threadIdx.x;
    const int warp = tid >> 5;
    const int lane = tid & 31;
    const int wm   = warp & 1;
    const int wn   = warp >> 1;
    const int lr = lane & 15;
    const int lh = lane >> 4;
    const int m_tile = blockIdx.y * 128;
    const int n_tile = blockIdx.x * 128;

    float acc[4][8][4];
#pragma unroll
    for (int i = 0; i < 4; i++)
#pragma unroll
        for (int j = 0; j < 8; j++)
#pragma unroll
            for (int q = 0; q < 4; q++) acc[i][j][q] = 0.f;

    gemm_mainloop(sbuf, acc, g_a, g_w + (size_t)3 * D_MODEL * D_MODEL,
                  m_tile, n_tile, 0, 16, 0, tid, wm, wn, lr, lh);

    const int qrow = lane >> 2;
    const int qcol = (lane & 3) * 2;
#pragma unroll
    for (int mf = 0; mf < 4; mf++)
#pragma unroll
        for (int nf = 0; nf < 8; nf++) {
            int n = n_tile + wn * 64 + nf * 8 + qcol;
#pragma unroll
            for (int hhalf = 0; hhalf < 2; hhalf++) {
                int m = m_tile + wm * 64 + mf * 16 + qrow + hhalf * 8;
                *(float2*)(C + (size_t)m * 1024 + n) =
                    make_float2(acc[mf][nf][hhalf * 2], acc[mf][nf][hhalf * 2 + 1]);
            }
        }
}

// ---------------------------------------------------------------------------
// K_proj / V_proj with inline reduce + RoPE(K).  Grid (BH, 8), 256 threads.
// ---------------------------------------------------------------------------
__device__ __forceinline__ float tril_dot(const float* __restrict__ pr,
                                          const float Ts[128][9], int d, int p)
{
    float s0 = 0.f, s1 = 0.f, s2 = 0.f, s3 = 0.f;
    int l = 0;
    for (; l + 3 <= p; l += 4) {
        s0 = fmaf(pr[l],     Ts[l][d],     s0);
        s1 = fmaf(pr[l + 1], Ts[l + 1][d], s1);
        s2 = fmaf(pr[l + 2], Ts[l + 2][d], s2);
        s3 = fmaf(pr[l + 3], Ts[l + 3][d], s3);
    }
    for (; l <= p; l++) s0 = fmaf(pr[l], Ts[l][d], s0);
    return (s0 + s1) + (s2 + s3);
}

__global__ void __launch_bounds__(256)
proj_kernel(const float* __restrict__ kpm, const float* __restrict__ vpm,
            const float* __restrict__ fcos, const float* __restrict__ fsin)
{
    __shared__ float Ts[128][9];
    const int bh = blockIdx.x;
    const int b  = bh >> 4;
    const int hh = bh & 15;
    const int d0 = blockIdx.y * 8;
    const int tid = threadIdx.x;

    // ---- K: sum 4 k-split partials, RoPE pairs ----
    for (int idx = tid; idx < 128 * 4; idx += 256) {
        int l = idx >> 2, dp = (idx & 3) * 2;
        size_t rem = (size_t)(b * 128 + l) * 1024 + hh * 64 + d0 + dp;
        float2 s  = *(const float2*)(g_kvpart + rem);
        float2 p1 = *(const float2*)(g_kvpart + KSLICE + rem);
        float2 p2 = *(const float2*)(g_kvpart + 2 * KSLICE + rem);
        float2 p3 = *(const float2*)(g_kvpart + 3 * KSLICE + rem);
        s.x += p1.x; s.y += p1.y;
        s.x += p2.x; s.y += p2.y;
        s.x += p3.x; s.y += p3.y;
        int j = (d0 + dp) >> 1;
        float c0 = __ldg(fcos + l * 32 + j);
        float s0 = __ldg(fsin + l * 32 + j);
        Ts[l][dp]     = s.x * c0 - s.y * s0;
        Ts[l][dp + 1] = s.x * s0 + s.y * c0;
    }
    __syncthreads();
#pragma unroll
    for (int t = 0; t < 4; t++) {
        int o = tid + t * 256;
        int p = o >> 3, d = o & 7;
        float s = tril_dot(kpm + (size_t)p * 4096, Ts, d, p);
        g_kp[(size_t)bh * 8192 + p * 64 + (d0 + d)] = __float2half_rn(s);
    }
    __syncthreads();

    // ---- V: sum 4 partials ----
    for (int idx = tid; idx < 128 * 8; idx += 256) {
        int l = idx >> 3, d = idx & 7;
        size_t rem = (size_t)(b * 128 + l) * 1024 + hh * 64 + d0 + d;
        float s = g_kvpart[4 * KSLICE + rem];
        s += g_kvpart[5 * KSLICE + rem];
        s += g_kvpart[6 * KSLICE + rem];
        s += g_kvpart[7 * KSLICE + rem];
        Ts[l][d] = s;
    }
    __syncthreads();
#pragma unroll
    for (int t = 0; t < 4; t++) {
        int o = tid + t * 256;
        int p = o >> 3, d = o & 7;
        float s = tril_dot(vpm + (size_t)p * 4096, Ts, d, p);
        g_vt[(size_t)bh * 8192 + (d0 + d) * 128 + p] = __float2half_rn(s);
    }
}

// ---------------------------------------------------------------------------
// Flash-style mma attention.  Q arrives pre-scaled by 0.125 (no scale pass).
// ---------------------------------------------------------------------------
#define AT_Q  0
#define AT_K  18432
#define AT_VT 36864
#define ATTN_SMEM 54272

__global__ void __launch_bounds__(256)
attn_kernel()
{
    extern __shared__ char smem[];
    const int bh = blockIdx.y;
    const int b  = bh >> 4;
    const int hh = bh & 15;
    const int l0 = blockIdx.x * 128;
    const int tid  = threadIdx.x;
    const int wp   = tid >> 5;
    const int lane = tid & 31;
    const int lr   = lane & 15;
    const int lh   = lane >> 4;
    const int qrow = lane >> 2;
    const int qcol = (lane & 3) * 2;

    const size_t qbase = (size_t)(b * L_SEQ + l0) * 1024 + hh * 64;
#pragma unroll
    for (int t = 0; t < 4; t++) {
        int i = tid + t * 256;
        int r = i >> 3, c = i & 7;
        cpa16(sptr(smem + AT_Q + r * 144 + c * 16), g_q  + qbase + (size_t)r * 1024 + c * 8);
        cpa16(sptr(smem + AT_K + r * 144 + c * 16), g_kp + (size_t)bh * 8192 + r * 64 + c * 8);
        int rv = i >> 4, cv = i & 15;
        cpa16(sptr(smem + AT_VT + rv * 272 + cv * 16), g_vt + (size_t)bh * 8192 + rv * 128 + cv * 8);
    }
    asm volatile("cp.async.commit_group;" ::: "memory");
    asm volatile("cp.async.wait_group 0;" ::: "memory");
    __syncthreads();

    float acc[16][4];
#pragma unroll
    for (int i = 0; i < 16; i++)
#pragma unroll
        for (int q = 0; q < 4; q++) acc[i][q] = 0.f;

#pragma unroll
    for (int ks = 0; ks < 4; ks++) {
        uint32_t aq[4];
        ldm4(aq, sptr(smem + AT_Q + (wp * 16 + lr) * 144 + ks * 32 + lh * 16));
#pragma unroll
        for (int g = 0; g < 8; g++) {
            uint32_t bk[4];
            ldm4(bk, sptr(smem + AT_K + (g * 16 + lr) * 144 + ks * 32 + lh * 16));
            mma_f16(acc[2*g],   aq, bk[0], bk[2]);
            mma_f16(acc[2*g+1], aq, bk[1], bk[3]);
        }
    }

    if (blockIdx.x == 0) {
        const int r0 = wp * 16 + qrow;
        const int r1 = r0 + 8;
#pragma unroll
        for (int nf = 0; nf < 16; nf++) {
            int p0 = nf * 8 + qcol;
            if (p0 > r0)     acc[nf][0] = -1e30f;
            if (p0 + 1 > r0) acc[nf][1] = -1e30f;
            if (p0 > r1)     acc[nf][2] = -1e30f;
            if (p0 + 1 > r1) acc[nf][3] = -1e30f;
        }
    }

    float mx0 = -1e30f, mx1 = -1e30f;
#pragma unroll
    for (int nf = 0; nf < 16; nf++) {
        mx0 = fmaxf(mx0, fmaxf(acc[nf][0], acc[nf][1]));
        mx1 = fmaxf(mx1, fmaxf(acc[nf][2], acc[nf][3]));
    }
    mx0 = fmaxf(mx0, __shfl_xor_sync(0xffffffffu, mx0, 1));
    mx0 = fmaxf(mx0, __shfl_xor_sync(0xffffffffu, mx0, 2));
    mx1 = fmaxf(mx1, __shfl_xor_sync(0xffffffffu, mx1, 1));
    mx1 = fmaxf(mx1, __shfl_xor_sync(0xffffffffu, mx1, 2));

    float s0 = 0.f, s1 = 0.f;
#pragma unroll
    for (int nf = 0; nf < 16; nf++) {
        acc[nf][0] = __expf(acc[nf][0] - mx0);
        acc[nf][1] = __expf(acc[nf][1] - mx0);
        acc[nf][2] = __expf(acc[nf][2] - mx1);
        acc[nf][3] = __expf(acc[nf][3] - mx1);
        s0 += acc[nf][0] + acc[nf][1];
        s1 += acc[nf][2] + acc[nf][3];
    }
    s0 += __shfl_xor_sync(0xffffffffu, s0, 1);
    s0 += __shfl_xor_sync(0xffffffffu, s0, 2);
    s1 += __shfl_xor_sync(0xffffffffu, s1, 1);
    s1 += __shfl_xor_sync(0xffffffffu, s1, 2);
    const float inv0 = 1.0f / s0;
    const float inv1 = 1.0f / s1;

    float o[8][4];
#pragma unroll
    for (int i = 0; i < 8; i++)
#pragma unroll
        for (int q = 0; q < 4; q++) o[i][q] = 0.f;

#pragma unroll
    for (int kc = 0; kc < 8; kc++) {
        uint32_t aw[4];
        aw[0] = pack2h(acc[2*kc][0],   acc[2*kc][1]);
        aw[1] = pack2h(acc[2*kc][2],   acc[2*kc][3]);
        aw[2] = pack2h(acc[2*kc+1][0], acc[2*kc+1][1]);
        aw[3] = pack2h(acc[2*kc+1][2], acc[2*kc+1][3]);
#pragma unroll
        for (int g = 0; g < 4; g++) {
            uint32_t bv[4];
            ldm4(bv, sptr(smem + AT_VT + (g * 16 + lr) * 272 + kc * 32 + lh * 16));
            mma_f16(o[2*g],   aw, bv[0], bv[2]);
            mma_f16(o[2*g+1], aw, bv[1], bv[3]);
        }
    }

    const size_t row0 = (size_t)(b * L_SEQ + l0 + wp * 16 + qrow);
    const size_t row1 = row0 + 8;
#pragma unroll
    for (int nf = 0; nf < 8; nf++) {
        int col = hh * 64 + nf * 8 + qcol;
        *(uint32_t*)(g_a + row0 * 1024 + col) = pack2h(o[nf][0] * inv0, o[nf][1] * inv0);
        *(uint32_t*)(g_a + row1 * 1024 + col) = pack2h(o[nf][2] * inv1, o[nf][3] * inv1);
    }
}

// ---------------------------------------------------------------------------
extern "C" void kernel_launch(void* const* d_in, const int* in_sizes, int n_in,
                              void* d_out, int out_size)
{
    const float* x    = (const float*)d_in[0];
    const float* fcos = (const float*)d_in[1];
    const float* fsin = (const float*)d_in[2];
    const float* Wq   = (const float*)d_in[3];
    const float* Wk   = (const float*)d_in[4];
    const float* Wv   = (const float*)d_in[5];
    const float* Wo   = (const float*)d_in[6];
    const float* kpm  = (const float*)d_in[7];
    const float* vpm  = (const float*)d_in[8];
    float* out = (float*)d_out;

    cudaFuncSetAttribute(attn_kernel,
                         cudaFuncAttributeMaxDynamicSharedMemorySize, ATTN_SMEM);
    cudaFuncSetAttribute(gemm_q_kv,
                         cudaFuncAttributeMaxDynamicSharedMemorySize, SM_GEMM);
    cudaFuncSetAttribute(gemm_wo,
                         cudaFuncAttributeMaxDynamicSharedMemorySize, SM_GEMM);

    // fp32 -> fp16 converts (one launch)
    convert_all<<<4096, 256>>>(x, Wq, Wk, Wv, Wo);

    // fused: Q = rope(x @ Wq^T)*0.125  +  split-K KV partials (tail-filled)
    gemm_q_kv<<<dim3(8, 160), 128, SM_GEMM>>>(fcos, fsin);

    // Linformer tril projections (inline reduce + RoPE(K))
    proj_kernel<<<dim3(BH, 8), 256>>>(kpm, vpm, fcos, fsin);

    // flash-style mma attention
    attn_kernel<<<dim3(L_SEQ / 128, BH), 256, ATTN_SMEM>>>();

    // out = attn @ Wo^T
    gemm_wo<<<dim3(8, 128), 128, SM_GEMM>>>(out);
}